// round 1
// baseline (speedup 1.0000x reference)
#include <cuda_runtime.h>
#include <math.h>

#define Bsz 1024
#define Nn  100
#define Hh  256
#define H3  768

// ---------------- static device scratch (no allocations allowed) ----------------
__device__ float g_G[Bsz*Nn*H3];      // enc @ W_e^T + b_ih1   (314.6 MB)
__device__ float g_ref[Bsz*Nn*Hh];    // enc @ W_ref           (104.9 MB)
__device__ float g_G0[Bsz*H3];        // ctx0 path
__device__ float g_mean[Bsz*Hh];
__device__ float g_W1T[Hh*H3];        // W_ih1[:, :256]^T  -> [k][j]
__device__ float g_W2T[Hh*H3];        // W_ih2^T           -> [k][j]
__device__ float g_bias0[H3];         // b_ih1 + w_D (for ctx0 where D=1)
__device__ float g_h1[Bsz*Hh];
__device__ float g_gi2[Bsz*H3];
__device__ float g_h2[Bsz*Hh];
__device__ float g_q[Bsz*Hh];
__device__ unsigned char g_mask[Bsz*Nn];
__device__ int   g_nxt[Bsz];
__device__ float g_ll[Bsz];
__device__ int   g_pi[Bsz*Nn];

// ---------------- math helpers (accuracy ~2e-7 abs; argmax-safe) ----------------
__device__ __forceinline__ float fast_tanh(float x) {
    float ax = fabsf(x);
    float e  = __expf(-2.0f * ax);            // MUFU.EX2, rel err ~2^-22
    float t  = __fdividef(1.0f - e, 1.0f + e);
    return copysignf(t, x);
}
__device__ __forceinline__ float sigmoidf_(float x) {
    return __fdividef(1.0f, 1.0f + __expf(-x));
}

// ---------------- precompute kernels ----------------
__global__ void k_prep(const float* __restrict__ W_ih1,
                       const float* __restrict__ W_ih2,
                       const float* __restrict__ b_ih1) {
    int i = blockIdx.x * 256 + threadIdx.x;   // over Hh*H3 = 196608
    if (i < Hh*H3) {
        int k = i / H3, j = i % H3;
        g_W1T[i] = W_ih1[j*257 + k];
        g_W2T[i] = W_ih2[j*256 + k];
    }
    if (i < H3) g_bias0[i] = b_ih1[i] + W_ih1[i*257 + 256];
}

__global__ void k_mean(const float* __restrict__ enc) {
    int b = blockIdx.x, h = threadIdx.x;
    float s = 0.f;
    for (int n = 0; n < Nn; n++) s += enc[(b*Nn + n)*Hh + h];
    g_mean[b*Hh + h] = s / (float)Nn;
}

__global__ void k_init() {
    int i = blockIdx.x * 256 + threadIdx.x;
    if (i < Bsz) g_ll[i] = 0.f;
    if (i < Bsz*Nn) g_mask[i] = 0;
}

// ---------------- generic fp32 tiled GEMM: C = A[MxK] * B[KxN] + bias ----------------
template<int BM, int BN, int TM, int TN>
__global__ __launch_bounds__(256)
void k_sgemm(const float* __restrict__ A, const float* __restrict__ Bm,
             const float* __restrict__ bias, float* __restrict__ C,
             int M, int N, int K) {
    const int BK = 16;
    __shared__ float As[BK][BM];
    __shared__ float Bs[BK][BN];
    int tid = threadIdx.x;
    int tx  = tid % (BN / TN);
    int ty  = tid / (BN / TN);
    int m0  = blockIdx.y * BM, n0 = blockIdx.x * BN;

    float acc[TM][TN];
#pragma unroll
    for (int i = 0; i < TM; i++)
#pragma unroll
        for (int j = 0; j < TN; j++) acc[i][j] = 0.f;

    for (int k0 = 0; k0 < K; k0 += BK) {
        // load A tile (transposed into smem), float4 along K
#pragma unroll
        for (int r = 0; r < (BM*BK)/1024; r++) {
            int idx = tid + r * 256;
            int mm  = idx / (BK/4);
            int kk4 = idx % (BK/4);
            float4 a = *(const float4*)&A[(size_t)(m0 + mm)*K + k0 + kk4*4];
            As[kk4*4+0][mm] = a.x; As[kk4*4+1][mm] = a.y;
            As[kk4*4+2][mm] = a.z; As[kk4*4+3][mm] = a.w;
        }
        // load B tile, float4 along N
#pragma unroll
        for (int r = 0; r < (BK*BN)/1024; r++) {
            int idx = tid + r * 256;
            int kk  = idx / (BN/4);
            int nn4 = idx % (BN/4);
            *(float4*)&Bs[kk][nn4*4] = *(const float4*)&Bm[(size_t)(k0 + kk)*N + n0 + nn4*4];
        }
        __syncthreads();
#pragma unroll
        for (int kk = 0; kk < BK; kk++) {
            float ra[TM], rb[TN];
#pragma unroll
            for (int i = 0; i < TM; i += 4) *(float4*)&ra[i] = *(float4*)&As[kk][ty*TM + i];
#pragma unroll
            for (int j = 0; j < TN; j += 4) *(float4*)&rb[j] = *(float4*)&Bs[kk][tx*TN + j];
#pragma unroll
            for (int i = 0; i < TM; i++)
#pragma unroll
                for (int j = 0; j < TN; j++) acc[i][j] += ra[i] * rb[j];
        }
        __syncthreads();
    }
#pragma unroll
    for (int i = 0; i < TM; i++) {
        int m = m0 + ty*TM + i;
#pragma unroll
        for (int j = 0; j < TN; j += 4) {
            int n = n0 + tx*TN + j;
            float4 r;
            r.x = acc[i][j+0] + (bias ? bias[n+0] : 0.f);
            r.y = acc[i][j+1] + (bias ? bias[n+1] : 0.f);
            r.z = acc[i][j+2] + (bias ? bias[n+2] : 0.f);
            r.w = acc[i][j+3] + (bias ? bias[n+3] : 0.f);
            *(float4*)&C[(size_t)m*N + n] = r;
        }
    }
}

// ---------------- per-step kernels ----------------
// GRU1 with h=0: gi1 = (t==0 ? G0[b] : G[b,nxt] + D_t * w_D); h1 = (1-z)*n
__global__ void k_h1(const float* __restrict__ W_ih1,
                     const float* __restrict__ b_hh1, int t) {
    int b = blockIdx.x, j = threadIdx.x;
    int nx = (t == 0) ? 0 : g_nxt[b];
    const float* src = (t == 0) ? &g_G0[b*H3] : &g_G[((size_t)b*Nn + nx)*H3];
    float gr = src[j], gz = src[j+256], gn = src[j+512];
    if (t > 0) {
        float D = 1.f;
        for (int i = 0; i < t; i++) D -= 0.01f;   // replicate jax's repeated subtraction
        gr += D * W_ih1[(size_t)j*257 + 256];
        gz += D * W_ih1[(size_t)(j+256)*257 + 256];
        gn += D * W_ih1[(size_t)(j+512)*257 + 256];
    }
    float r = sigmoidf_(gr + b_hh1[j]);
    float z = sigmoidf_(gz + b_hh1[j+256]);
    float n = fast_tanh(gn + r * b_hh1[j+512]);
    g_h1[b*Hh + j] = (1.f - z) * n;
}

// GRU2 pointwise from gi2
__global__ void k_gru2(const float* __restrict__ b_hh2) {
    int i = blockIdx.x * 256 + threadIdx.x;   // B*H
    int b = i >> 8, j = i & 255;
    const float* gi = &g_gi2[(size_t)b*H3];
    float r = sigmoidf_(gi[j]     + b_hh2[j]);
    float z = sigmoidf_(gi[j+256] + b_hh2[j+256]);
    float n = fast_tanh(gi[j+512] + r * b_hh2[j+512]);
    g_h2[i] = (1.f - z) * n;
}

// attention + mask + argmax + log_softmax + state update, one block per batch
__global__ void k_attn(const float* __restrict__ v, int t) {
    int b = blockIdx.x;
    __shared__ __align__(16) float sq[Hh];
    __shared__ __align__(16) float sv[Hh];
    __shared__ float su[Nn];
    int tid = threadIdx.x;          // 256
    sq[tid] = g_q[b*Hh + tid];
    sv[tid] = v[tid];
    __syncthreads();
    int w = tid >> 5, l = tid & 31;
    for (int n = w; n < Nn; n += 8) {
        const float4* rr = (const float4*)&g_ref[((size_t)b*Nn + n)*Hh];
        float s = 0.f;
#pragma unroll
        for (int c = 0; c < 2; c++) {
            float4 r4 = rr[c*32 + l];
            float4 q4 = *(const float4*)&sq[(c*32 + l)*4];
            float4 v4 = *(const float4*)&sv[(c*32 + l)*4];
            s += fast_tanh(q4.x + r4.x) * v4.x;
            s += fast_tanh(q4.y + r4.y) * v4.y;
            s += fast_tanh(q4.z + r4.z) * v4.z;
            s += fast_tanh(q4.w + r4.w) * v4.w;
        }
#pragma unroll
        for (int o = 16; o; o >>= 1) s += __shfl_xor_sync(~0u, s, o);
        if (l == 0)
            su[n] = g_mask[b*Nn + n] ? -1000000000.0f : 10.f * fast_tanh(s);
    }
    __syncthreads();
    if (w == 0) {
        float best = -INFINITY; int bi = 0x7fffffff;
        for (int n = l; n < Nn; n += 32) {
            float uu = su[n];
            if (uu > best) { best = uu; bi = n; }   // ascending n keeps first max
        }
#pragma unroll
        for (int o = 16; o; o >>= 1) {
            float ov = __shfl_xor_sync(~0u, best, o);
            int   oi = __shfl_xor_sync(~0u, bi, o);
            if (ov > best || (ov == best && oi < bi)) { best = ov; bi = oi; }
        }
        float se = 0.f;
        for (int n = l; n < Nn; n += 32) se += __expf(su[n] - best);
#pragma unroll
        for (int o = 16; o; o >>= 1) se += __shfl_xor_sync(~0u, se, o);
        if (l == 0) {
            float logp = -__logf(se);               // u[argmax]==max
            g_ll[b] = (t == 0 ? 0.f : g_ll[b]) + logp;
            g_nxt[b] = bi;
            g_pi[b*Nn + t] = bi;
            g_mask[b*Nn + bi] = 1;
        }
    }
}

// tour cost + output write
__global__ void k_cost(const float* __restrict__ x, float* __restrict__ out) {
    int b = blockIdx.x;
    __shared__ float sred[128];
    int tid = threadIdx.x;   // 128
    float s = 0.f;
    for (int tt = tid; tt < Nn; tt += 128) {
        int a = g_pi[b*Nn + tt];
        int c = g_pi[b*Nn + ((tt + 1 == Nn) ? 0 : tt + 1)];
        float ax = x[((size_t)b*Nn + a)*2],     ay = x[((size_t)b*Nn + a)*2 + 1];
        float cx = x[((size_t)b*Nn + c)*2],     cy = x[((size_t)b*Nn + c)*2 + 1];
        float dx = ax - cx, dy = ay - cy;
        s += sqrtf(dx*dx + dy*dy);
    }
    sred[tid] = s; __syncthreads();
    for (int o = 64; o; o >>= 1) { if (tid < o) sred[tid] += sred[tid + o]; __syncthreads(); }
    if (tid == 0) { out[b] = sred[0]; out[Bsz + b] = g_ll[b]; }
}

// ---------------- launcher ----------------
extern "C" void kernel_launch(void* const* d_in, const int* in_sizes, int n_in,
                              void* d_out, int out_size) {
    const float* x     = (const float*)d_in[0];
    const float* enc   = (const float*)d_in[1];
    const float* W_ih1 = (const float*)d_in[2];
    const float* b_ih1 = (const float*)d_in[4];
    const float* b_hh1 = (const float*)d_in[5];
    const float* W_ih2 = (const float*)d_in[6];
    const float* b_ih2 = (const float*)d_in[8];
    const float* b_hh2 = (const float*)d_in[9];
    const float* W_q   = (const float*)d_in[10];
    const float* W_ref = (const float*)d_in[11];
    const float* v     = (const float*)d_in[12];
    float* out = (float*)d_out;

    float *G, *REF, *G0, *MEAN, *W1T, *W2T, *BIAS0, *H1, *GI2, *H2, *Q;
    cudaGetSymbolAddress((void**)&G,    g_G);
    cudaGetSymbolAddress((void**)&REF,  g_ref);
    cudaGetSymbolAddress((void**)&G0,   g_G0);
    cudaGetSymbolAddress((void**)&MEAN, g_mean);
    cudaGetSymbolAddress((void**)&W1T,  g_W1T);
    cudaGetSymbolAddress((void**)&W2T,  g_W2T);
    cudaGetSymbolAddress((void**)&BIAS0,g_bias0);
    cudaGetSymbolAddress((void**)&H1,   g_h1);
    cudaGetSymbolAddress((void**)&GI2,  g_gi2);
    cudaGetSymbolAddress((void**)&H2,   g_h2);
    cudaGetSymbolAddress((void**)&Q,    g_q);

    k_prep<<<768, 256>>>(W_ih1, W_ih2, b_ih1);
    k_mean<<<Bsz, 256>>>(enc);
    k_init<<<(Bsz*Nn + 255)/256, 256>>>();

    // G = enc @ W1T + b_ih1   [102400 x 768], K=256
    k_sgemm<128,64,8,4><<<dim3(H3/64, (Bsz*Nn)/128), 256>>>(enc, W1T, b_ih1, G, Bsz*Nn, H3, Hh);
    // ref = enc @ W_ref       [102400 x 256]
    k_sgemm<128,64,8,4><<<dim3(Hh/64, (Bsz*Nn)/128), 256>>>(enc, W_ref, nullptr, REF, Bsz*Nn, Hh, Hh);
    // G0 = mean @ W1T + (b_ih1 + w_D)   [1024 x 768]
    k_sgemm<64,64,4,4><<<dim3(H3/64, Bsz/64), 256>>>(MEAN, W1T, BIAS0, G0, Bsz, H3, Hh);

    for (int t = 0; t < Nn; t++) {
        k_h1<<<Bsz, 256>>>(W_ih1, b_hh1, t);
        // gi2 = h1 @ W2T + b_ih2   [1024 x 768]
        k_sgemm<64,64,4,4><<<dim3(H3/64, Bsz/64), 256>>>(H1, W2T, b_ih2, GI2, Bsz, H3, Hh);
        k_gru2<<<Bsz, 256>>>(b_hh2);
        // q = h2 @ W_q   [1024 x 256]
        k_sgemm<64,64,4,4><<<dim3(Hh/64, Bsz/64), 256>>>(H2, W_q, nullptr, Q, Bsz, Hh, Hh);
        k_attn<<<Bsz, 256>>>(v, t);
    }
    k_cost<<<Bsz, 128>>>(x, out);
}

// round 2
// speedup vs baseline: 1.0082x; 1.0082x over previous
#include <cuda_runtime.h>
#include <math.h>

#define Bsz 1024
#define Nn  100
#define Hh  256
#define H3  768

// ---------------- static device scratch (no allocations allowed) ----------------
__device__ float g_G[Bsz*Nn*H3];      // enc @ W_e^T + b_ih1   (314.6 MB)
__device__ float g_ref[Bsz*Nn*Hh];    // enc @ W_ref           (104.9 MB)
__device__ float g_G0[Bsz*H3];        // ctx0 path
__device__ float g_mean[Bsz*Hh];
__device__ float g_W1T[Hh*H3];        // W_ih1[:, :256]^T  -> [k][j]
__device__ float g_W2T[Hh*H3];        // W_ih2^T           -> [k][j]
__device__ float g_bias0[H3];         // b_ih1 + w_D (for ctx0 where D=1)
__device__ float g_h1[Bsz*Hh];
__device__ float g_gi2[Bsz*H3];
__device__ float g_h2[Bsz*Hh];
__device__ float g_q[Bsz*Hh];
__device__ unsigned char g_mask[Bsz*Nn];
__device__ int   g_nxt[Bsz];
__device__ float g_ll[Bsz];
__device__ int   g_pi[Bsz*Nn];

// ---------------- math helpers (accuracy ~2e-7 abs; argmax-safe) ----------------
__device__ __forceinline__ float fast_tanh(float x) {
    float ax = fabsf(x);
    float e  = __expf(-2.0f * ax);            // MUFU.EX2, rel err ~2^-22
    float t  = __fdividef(1.0f - e, 1.0f + e);
    return copysignf(t, x);
}
__device__ __forceinline__ float sigmoidf_(float x) {
    return __fdividef(1.0f, 1.0f + __expf(-x));
}

// ---------------- precompute kernels ----------------
__global__ void k_prep(const float* __restrict__ W_ih1,
                       const float* __restrict__ W_ih2,
                       const float* __restrict__ b_ih1) {
    int i = blockIdx.x * 256 + threadIdx.x;   // over Hh*H3 = 196608
    if (i < Hh*H3) {
        int k = i / H3, j = i % H3;
        g_W1T[i] = W_ih1[j*257 + k];
        g_W2T[i] = W_ih2[j*256 + k];
    }
    if (i < H3) g_bias0[i] = b_ih1[i] + W_ih1[i*257 + 256];
}

__global__ void k_mean(const float* __restrict__ enc) {
    int b = blockIdx.x, h = threadIdx.x;
    float s = 0.f;
    for (int n = 0; n < Nn; n++) s += enc[(b*Nn + n)*Hh + h];
    g_mean[b*Hh + h] = s / (float)Nn;
}

__global__ void k_init() {
    int i = blockIdx.x * 256 + threadIdx.x;
    if (i < Bsz) g_ll[i] = 0.f;
    if (i < Bsz*Nn) g_mask[i] = 0;
}

// ---------------- generic fp32 tiled GEMM: C = A[MxK] * B[KxN] + bias ----------------
template<int BM, int BN, int TM, int TN>
__global__ __launch_bounds__(256)
void k_sgemm(const float* __restrict__ A, const float* __restrict__ Bm,
             const float* __restrict__ bias, float* __restrict__ C,
             int M, int N, int K) {
    const int BK = 16;
    __shared__ float As[BK][BM];
    __shared__ float Bs[BK][BN];
    int tid = threadIdx.x;
    int tx  = tid % (BN / TN);
    int ty  = tid / (BN / TN);
    int m0  = blockIdx.y * BM, n0 = blockIdx.x * BN;

    float acc[TM][TN];
#pragma unroll
    for (int i = 0; i < TM; i++)
#pragma unroll
        for (int j = 0; j < TN; j++) acc[i][j] = 0.f;

    for (int k0 = 0; k0 < K; k0 += BK) {
        // load A tile (transposed into smem), float4 along K
#pragma unroll
        for (int r = 0; r < (BM*BK)/1024; r++) {
            int idx = tid + r * 256;
            int mm  = idx / (BK/4);
            int kk4 = idx % (BK/4);
            float4 a = *(const float4*)&A[(size_t)(m0 + mm)*K + k0 + kk4*4];
            As[kk4*4+0][mm] = a.x; As[kk4*4+1][mm] = a.y;
            As[kk4*4+2][mm] = a.z; As[kk4*4+3][mm] = a.w;
        }
        // load B tile, float4 along N
#pragma unroll
        for (int r = 0; r < (BK*BN)/1024; r++) {
            int idx = tid + r * 256;
            int kk  = idx / (BN/4);
            int nn4 = idx % (BN/4);
            *(float4*)&Bs[kk][nn4*4] = *(const float4*)&Bm[(size_t)(k0 + kk)*N + n0 + nn4*4];
        }
        __syncthreads();
#pragma unroll
        for (int kk = 0; kk < BK; kk++) {
            float ra[TM], rb[TN];
#pragma unroll
            for (int i = 0; i < TM; i += 4) *(float4*)&ra[i] = *(float4*)&As[kk][ty*TM + i];
#pragma unroll
            for (int j = 0; j < TN; j += 4) *(float4*)&rb[j] = *(float4*)&Bs[kk][tx*TN + j];
#pragma unroll
            for (int i = 0; i < TM; i++)
#pragma unroll
                for (int j = 0; j < TN; j++) acc[i][j] += ra[i] * rb[j];
        }
        __syncthreads();
    }
#pragma unroll
    for (int i = 0; i < TM; i++) {
        int m = m0 + ty*TM + i;
#pragma unroll
        for (int j = 0; j < TN; j += 4) {
            int n = n0 + tx*TN + j;
            float4 r;
            r.x = acc[i][j+0] + (bias ? bias[n+0] : 0.f);
            r.y = acc[i][j+1] + (bias ? bias[n+1] : 0.f);
            r.z = acc[i][j+2] + (bias ? bias[n+2] : 0.f);
            r.w = acc[i][j+3] + (bias ? bias[n+3] : 0.f);
            *(float4*)&C[(size_t)m*N + n] = r;
        }
    }
}

// ---------------- per-step kernels ----------------
// GRU1 with h=0: gi1 = (t==0 ? G0[b] : G[b,nxt] + D_t * w_D); h1 = (1-z)*n
__global__ void k_h1(const float* __restrict__ W_ih1,
                     const float* __restrict__ b_hh1, int t) {
    int b = blockIdx.x, j = threadIdx.x;
    int nx = (t == 0) ? 0 : g_nxt[b];
    const float* src = (t == 0) ? &g_G0[b*H3] : &g_G[((size_t)b*Nn + nx)*H3];
    float gr = src[j], gz = src[j+256], gn = src[j+512];
    if (t > 0) {
        float D = 1.f;
        for (int i = 0; i < t; i++) D -= 0.01f;   // replicate jax's repeated subtraction
        gr += D * W_ih1[(size_t)j*257 + 256];
        gz += D * W_ih1[(size_t)(j+256)*257 + 256];
        gn += D * W_ih1[(size_t)(j+512)*257 + 256];
    }
    float r = sigmoidf_(gr + b_hh1[j]);
    float z = sigmoidf_(gz + b_hh1[j+256]);
    float n = fast_tanh(gn + r * b_hh1[j+512]);
    g_h1[b*Hh + j] = (1.f - z) * n;
}

// GRU2 pointwise from gi2
__global__ void k_gru2(const float* __restrict__ b_hh2) {
    int i = blockIdx.x * 256 + threadIdx.x;   // B*H
    int b = i >> 8, j = i & 255;
    const float* gi = &g_gi2[(size_t)b*H3];
    float r = sigmoidf_(gi[j]     + b_hh2[j]);
    float z = sigmoidf_(gi[j+256] + b_hh2[j+256]);
    float n = fast_tanh(gi[j+512] + r * b_hh2[j+512]);
    g_h2[i] = (1.f - z) * n;
}

// attention + mask + argmax + log_softmax + state update, one block per batch
__global__ void k_attn(const float* __restrict__ v, int t) {
    int b = blockIdx.x;
    __shared__ __align__(16) float sq[Hh];
    __shared__ __align__(16) float sv[Hh];
    __shared__ float su[Nn];
    int tid = threadIdx.x;          // 256
    sq[tid] = g_q[b*Hh + tid];
    sv[tid] = v[tid];
    __syncthreads();
    int w = tid >> 5, l = tid & 31;
    for (int n = w; n < Nn; n += 8) {
        const float4* rr = (const float4*)&g_ref[((size_t)b*Nn + n)*Hh];
        float s = 0.f;
#pragma unroll
        for (int c = 0; c < 2; c++) {
            float4 r4 = rr[c*32 + l];
            float4 q4 = *(const float4*)&sq[(c*32 + l)*4];
            float4 v4 = *(const float4*)&sv[(c*32 + l)*4];
            s += fast_tanh(q4.x + r4.x) * v4.x;
            s += fast_tanh(q4.y + r4.y) * v4.y;
            s += fast_tanh(q4.z + r4.z) * v4.z;
            s += fast_tanh(q4.w + r4.w) * v4.w;
        }
#pragma unroll
        for (int o = 16; o; o >>= 1) s += __shfl_xor_sync(~0u, s, o);
        if (l == 0)
            su[n] = g_mask[b*Nn + n] ? -1000000000.0f : 10.f * fast_tanh(s);
    }
    __syncthreads();
    if (w == 0) {
        float best = -INFINITY; int bi = 0x7fffffff;
        for (int n = l; n < Nn; n += 32) {
            float uu = su[n];
            if (uu > best) { best = uu; bi = n; }   // ascending n keeps first max
        }
#pragma unroll
        for (int o = 16; o; o >>= 1) {
            float ov = __shfl_xor_sync(~0u, best, o);
            int   oi = __shfl_xor_sync(~0u, bi, o);
            if (ov > best || (ov == best && oi < bi)) { best = ov; bi = oi; }
        }
        float se = 0.f;
        for (int n = l; n < Nn; n += 32) se += __expf(su[n] - best);
#pragma unroll
        for (int o = 16; o; o >>= 1) se += __shfl_xor_sync(~0u, se, o);
        if (l == 0) {
            float logp = -__logf(se);               // u[argmax]==max
            g_ll[b] = (t == 0 ? 0.f : g_ll[b]) + logp;
            g_nxt[b] = bi;
            g_pi[b*Nn + t] = bi;
            g_mask[b*Nn + bi] = 1;
        }
    }
}

// tour cost + output write
__global__ void k_cost(const float* __restrict__ x, float* __restrict__ out) {
    int b = blockIdx.x;
    __shared__ float sred[128];
    int tid = threadIdx.x;   // 128
    float s = 0.f;
    for (int tt = tid; tt < Nn; tt += 128) {
        int a = g_pi[b*Nn + tt];
        int c = g_pi[b*Nn + ((tt + 1 == Nn) ? 0 : tt + 1)];
        float ax = x[((size_t)b*Nn + a)*2],     ay = x[((size_t)b*Nn + a)*2 + 1];
        float cx = x[((size_t)b*Nn + c)*2],     cy = x[((size_t)b*Nn + c)*2 + 1];
        float dx = ax - cx, dy = ay - cy;
        s += sqrtf(dx*dx + dy*dy);
    }
    sred[tid] = s; __syncthreads();
    for (int o = 64; o; o >>= 1) { if (tid < o) sred[tid] += sred[tid + o]; __syncthreads(); }
    if (tid == 0) { out[b] = sred[0]; out[Bsz + b] = g_ll[b]; }
}

// ---------------- launcher ----------------
extern "C" void kernel_launch(void* const* d_in, const int* in_sizes, int n_in,
                              void* d_out, int out_size) {
    const float* x     = (const float*)d_in[0];
    const float* enc   = (const float*)d_in[1];
    const float* W_ih1 = (const float*)d_in[2];
    const float* b_ih1 = (const float*)d_in[4];
    const float* b_hh1 = (const float*)d_in[5];
    const float* W_ih2 = (const float*)d_in[6];
    const float* b_ih2 = (const float*)d_in[8];
    const float* b_hh2 = (const float*)d_in[9];
    const float* W_q   = (const float*)d_in[10];
    const float* W_ref = (const float*)d_in[11];
    const float* v     = (const float*)d_in[12];
    float* out = (float*)d_out;

    float *G, *REF, *G0, *MEAN, *W1T, *W2T, *BIAS0, *H1, *GI2, *H2, *Q;
    cudaGetSymbolAddress((void**)&G,    g_G);
    cudaGetSymbolAddress((void**)&REF,  g_ref);
    cudaGetSymbolAddress((void**)&G0,   g_G0);
    cudaGetSymbolAddress((void**)&MEAN, g_mean);
    cudaGetSymbolAddress((void**)&W1T,  g_W1T);
    cudaGetSymbolAddress((void**)&W2T,  g_W2T);
    cudaGetSymbolAddress((void**)&BIAS0,g_bias0);
    cudaGetSymbolAddress((void**)&H1,   g_h1);
    cudaGetSymbolAddress((void**)&GI2,  g_gi2);
    cudaGetSymbolAddress((void**)&H2,   g_h2);
    cudaGetSymbolAddress((void**)&Q,    g_q);

    k_prep<<<768, 256>>>(W_ih1, W_ih2, b_ih1);
    k_mean<<<Bsz, 256>>>(enc);
    k_init<<<(Bsz*Nn + 255)/256, 256>>>();

    // G = enc @ W1T + b_ih1   [102400 x 768], K=256
    k_sgemm<128,64,8,4><<<dim3(H3/64, (Bsz*Nn)/128), 256>>>(enc, W1T, b_ih1, G, Bsz*Nn, H3, Hh);
    // ref = enc @ W_ref       [102400 x 256]
    k_sgemm<128,64,8,4><<<dim3(Hh/64, (Bsz*Nn)/128), 256>>>(enc, W_ref, nullptr, REF, Bsz*Nn, Hh, Hh);
    // G0 = mean @ W1T + (b_ih1 + w_D)   [1024 x 768]
    k_sgemm<64,64,4,4><<<dim3(H3/64, Bsz/64), 256>>>(MEAN, W1T, BIAS0, G0, Bsz, H3, Hh);

    for (int t = 0; t < Nn; t++) {
        k_h1<<<Bsz, 256>>>(W_ih1, b_hh1, t);
        // gi2 = h1 @ W2T + b_ih2   [1024 x 768]
        k_sgemm<64,64,4,4><<<dim3(H3/64, Bsz/64), 256>>>(H1, W2T, b_ih2, GI2, Bsz, H3, Hh);
        k_gru2<<<Bsz, 256>>>(b_hh2);
        // q = h2 @ W_q   [1024 x 256]
        k_sgemm<64,64,4,4><<<dim3(Hh/64, Bsz/64), 256>>>(H2, W_q, nullptr, Q, Bsz, Hh, Hh);
        k_attn<<<Bsz, 256>>>(v, t);
    }
    k_cost<<<Bsz, 128>>>(x, out);
}

// round 3
// speedup vs baseline: 1.3571x; 1.3461x over previous
#include <cuda_runtime.h>
#include <math.h>

#define Bsz 1024
#define Nn  100
#define Hh  256
#define H3  768

__device__ float g_G[Bsz*Nn*H3];
__device__ float g_ref[Bsz*Nn*Hh];
__device__ float g_G0[Bsz*H3];
__device__ float g_mean[Bsz*Hh];
__device__ float g_W1T[Hh*H3];
__device__ float g_W2T[Hh*H3];
__device__ float g_bias0[H3];
__device__ float g_wD[H3];

__device__ __forceinline__ float fast_tanh(float x) {
    float ax = fabsf(x);
    float e  = __expf(-2.0f * ax);
    float t  = __fdividef(1.0f - e, 1.0f + e);
    return copysignf(t, x);
}
__device__ __forceinline__ float sigmoidf_(float x) {
    return __fdividef(1.0f, 1.0f + __expf(-x));
}
// sum_i tanh(q_i+r_i)*v_i over 4 lanes, one RCP
__device__ __forceinline__ float tanh4dot(float4 q, float4 r, float4 v) {
    const float C = -2.8853900817779268f;   // -2*log2(e)
    float x0=q.x+r.x, x1=q.y+r.y, x2=q.z+r.z, x3=q.w+r.w;
    float e0=exp2f(fabsf(x0)*C), e1=exp2f(fabsf(x1)*C);
    float e2=exp2f(fabsf(x2)*C), e3=exp2f(fabsf(x3)*C);
    float a0=1.f+e0, a1=1.f+e1, a2=1.f+e2, a3=1.f+e3;
    float m0=(1.f-e0)*v.x, m1=(1.f-e1)*v.y, m2=(1.f-e2)*v.z, m3=(1.f-e3)*v.w;
    m0=__uint_as_float(__float_as_uint(m0)^(__float_as_uint(x0)&0x80000000u));
    m1=__uint_as_float(__float_as_uint(m1)^(__float_as_uint(x1)&0x80000000u));
    m2=__uint_as_float(__float_as_uint(m2)^(__float_as_uint(x2)&0x80000000u));
    m3=__uint_as_float(__float_as_uint(m3)^(__float_as_uint(x3)&0x80000000u));
    float p01=a0*a1, p23=a2*a3, d=p01*p23, rd;
    asm("rcp.approx.f32 %0, %1;" : "=f"(rd) : "f"(d));
    float num = fmaf(fmaf(m0,a1,m1*a0), p23, fmaf(m2,a3,m3*a2)*p01);
    return num * rd;
}
__device__ __forceinline__ void cp16(float* dst, const float* src) {
    unsigned d = (unsigned)__cvta_generic_to_shared(dst);
    asm volatile("cp.async.cg.shared.global [%0], [%1], 16;" :: "r"(d), "l"(src) : "memory");
}
#define CP_COMMIT() asm volatile("cp.async.commit_group;")
#define CP_WAIT0()  asm volatile("cp.async.wait_group 0;")

__global__ void k_prep(const float* __restrict__ W_ih1,
                       const float* __restrict__ W_ih2,
                       const float* __restrict__ b_ih1) {
    int i = blockIdx.x * 256 + threadIdx.x;
    if (i < Hh*H3) {
        int k = i / H3, j = i % H3;
        g_W1T[i] = W_ih1[j*257 + k];
        g_W2T[i] = W_ih2[j*256 + k];
    }
    if (i < H3) {
        float wd = W_ih1[i*257 + 256];
        g_wD[i] = wd;
        g_bias0[i] = b_ih1[i] + wd;
    }
}

__global__ void k_mean(const float* __restrict__ enc) {
    int b = blockIdx.x, h = threadIdx.x;
    float s = 0.f;
    for (int n = 0; n < Nn; n++) s += enc[(b*Nn + n)*Hh + h];
    g_mean[b*Hh + h] = s / (float)Nn;
}

template<int BM, int BN, int TM, int TN>
__global__ __launch_bounds__(256)
void k_sgemm(const float* __restrict__ A, const float* __restrict__ Bm,
             const float* __restrict__ bias, float* __restrict__ C,
             int M, int N, int K) {
    const int BK = 16;
    __shared__ float As[BK][BM];
    __shared__ float Bs[BK][BN];
    int tid = threadIdx.x;
    int tx = tid % (BN/TN), ty = tid / (BN/TN);
    int m0 = blockIdx.y * BM, n0 = blockIdx.x * BN;
    float acc[TM][TN];
#pragma unroll
    for (int i = 0; i < TM; i++)
#pragma unroll
        for (int j = 0; j < TN; j++) acc[i][j] = 0.f;
    for (int k0 = 0; k0 < K; k0 += BK) {
#pragma unroll
        for (int r = 0; r < (BM*BK)/1024; r++) {
            int idx = tid + r*256, mm = idx/(BK/4), kk4 = idx%(BK/4);
            float4 a = *(const float4*)&A[(size_t)(m0+mm)*K + k0 + kk4*4];
            As[kk4*4+0][mm]=a.x; As[kk4*4+1][mm]=a.y; As[kk4*4+2][mm]=a.z; As[kk4*4+3][mm]=a.w;
        }
#pragma unroll
        for (int r = 0; r < (BK*BN)/1024; r++) {
            int idx = tid + r*256, kk = idx/(BN/4), nn4 = idx%(BN/4);
            *(float4*)&Bs[kk][nn4*4] = *(const float4*)&Bm[(size_t)(k0+kk)*N + n0 + nn4*4];
        }
        __syncthreads();
#pragma unroll
        for (int kk = 0; kk < BK; kk++) {
            float ra[TM], rb[TN];
#pragma unroll
            for (int i = 0; i < TM; i += 4) *(float4*)&ra[i] = *(float4*)&As[kk][ty*TM+i];
#pragma unroll
            for (int j = 0; j < TN; j += 4) *(float4*)&rb[j] = *(float4*)&Bs[kk][tx*TN+j];
#pragma unroll
            for (int i = 0; i < TM; i++)
#pragma unroll
                for (int j = 0; j < TN; j++) acc[i][j] += ra[i]*rb[j];
        }
        __syncthreads();
    }
#pragma unroll
    for (int i = 0; i < TM; i++) {
        int m = m0 + ty*TM + i;
#pragma unroll
        for (int j = 0; j < TN; j += 4) {
            int n = n0 + tx*TN + j;
            float4 r;
            r.x = acc[i][j+0] + (bias ? bias[n+0] : 0.f);
            r.y = acc[i][j+1] + (bias ? bias[n+1] : 0.f);
            r.z = acc[i][j+2] + (bias ? bias[n+2] : 0.f);
            r.w = acc[i][j+3] + (bias ? bias[n+3] : 0.f);
            *(float4*)&C[(size_t)m*N + n] = r;
        }
    }
}

// ============ monolithic 100-step decode loop ============
#define SMEM_BYTES ((24576 + 2048*3 + 256 + 800)*4 + 8*4 + 1600)

__global__ __launch_bounds__(256, 1)
void k_loop(const float* __restrict__ G,  const float* __restrict__ G0,
            const float* __restrict__ REF, const float* __restrict__ W2T,
            const float* __restrict__ Wq,  const float* __restrict__ b_hh1,
            const float* __restrict__ b_ih2, const float* __restrict__ b_hh2,
            const float* __restrict__ v,   const float* __restrict__ wD,
            const float* __restrict__ x,   float* __restrict__ out) {
    extern __shared__ float sm[];
    float* shB   = sm;                    // 2 x 12288
    float* sh_h1 = sm + 24576;
    float* sh_h2 = sh_h1 + 2048;
    float* sh_q  = sh_h2 + 2048;
    float* sh_v  = sh_q + 2048;
    float* sh_su = sh_v + 256;
    int*   sh_nxt = (int*)(sh_su + 800);
    unsigned char* sh_mask = (unsigned char*)(sh_nxt + 8);
    unsigned char* sh_pi   = sh_mask + 800;

    const int tid = threadIdx.x, lane = tid & 31, w = tid >> 5;
    const int b0 = blockIdx.x * 8;

    for (int i = tid; i < 800; i += 256) sh_mask[i] = 0;
    sh_v[tid] = __ldg(v + tid);
    const float bi2r = __ldg(b_ih2 + tid),       bh2r = __ldg(b_hh2 + tid);
    const float bi2z = __ldg(b_ih2 + tid + 256), bh2z = __ldg(b_hh2 + tid + 256);
    const float bi2n = __ldg(b_ih2 + tid + 512), bh2n = __ldg(b_hh2 + tid + 512);

    // prefetch W2T tile0 -> buf0
#pragma unroll
    for (int p = 0; p < 12; p++) { int e = tid + p*256; cp16(shB + e*4, W2T + e*4); }
    CP_COMMIT();
    __syncthreads();

    float Dv = 1.0f, ll = 0.0f;

#pragma unroll 1
    for (int t = 0; t < Nn; t++) {
        // -- phase 1: GRU1 (h=0), warp w -> row w --
        {
            const float* gsrc = (t == 0) ? (G0 + (size_t)(b0 + w)*H3)
                                         : (G + ((size_t)(b0 + w)*Nn + sh_nxt[w])*H3);
#pragma unroll
            for (int c = 0; c < 8; c++) {
                int j = lane + 32*c;
                float gr = __ldg(gsrc+j), gz = __ldg(gsrc+j+256), gn = __ldg(gsrc+j+512);
                if (t > 0) {
                    gr = fmaf(Dv, __ldg(wD+j),     gr);
                    gz = fmaf(Dv, __ldg(wD+j+256), gz);
                    gn = fmaf(Dv, __ldg(wD+j+512), gn);
                }
                float rr = sigmoidf_(gr + __ldg(b_hh1+j));
                float zz = sigmoidf_(gz + __ldg(b_hh1+j+256));
                float nn = fast_tanh(fmaf(rr, __ldg(b_hh1+j+512), gn));
                sh_h1[w*256 + j] = (1.f - zz) * nn;
            }
        }
        // -- phase 2: GEMM2 (gi2 = h1 @ W2T), fused GRU2 epilogue --
        float acc0[8], acc1[8], acc2[8];
#pragma unroll
        for (int r = 0; r < 8; r++) { acc0[r]=0.f; acc1[r]=0.f; acc2[r]=0.f; }
#pragma unroll 1
        for (int tile = 0; tile < 16; tile++) {
            CP_WAIT0();
            __syncthreads();
            if (tile < 15) {
                const float* src = W2T + (tile+1)*12288;
                float* dst = shB + ((tile+1)&1)*12288;
#pragma unroll
                for (int p = 0; p < 12; p++) { int e = tid + p*256; cp16(dst + e*4, src + e*4); }
                CP_COMMIT();
            }
            const float* Bt = shB + (tile&1)*12288;
#pragma unroll
            for (int k4 = 0; k4 < 4; k4++) {
                float4 a[8];
#pragma unroll
                for (int r = 0; r < 8; r++)
                    a[r] = *(const float4*)(sh_h1 + r*256 + tile*16 + k4*4);
#pragma unroll
                for (int kk = 0; kk < 4; kk++) {
                    const float* Brow = Bt + (k4*4 + kk)*H3;
                    float bb0 = Brow[tid], bb1 = Brow[tid+256], bb2 = Brow[tid+512];
#pragma unroll
                    for (int r = 0; r < 8; r++) {
                        float av = (kk==0)?a[r].x:(kk==1)?a[r].y:(kk==2)?a[r].z:a[r].w;
                        acc0[r] = fmaf(av, bb0, acc0[r]);
                        acc1[r] = fmaf(av, bb1, acc1[r]);
                        acc2[r] = fmaf(av, bb2, acc2[r]);
                    }
                }
            }
        }
        // prefetch Wq tile0 -> buf0 (buf0 idle since GEMM2 tile14)
#pragma unroll
        for (int p = 0; p < 4; p++) { int e = tid + p*256; cp16(shB + e*4, Wq + e*4); }
        CP_COMMIT();
#pragma unroll
        for (int r = 0; r < 8; r++) {
            float rr = sigmoidf_((acc0[r] + bi2r) + bh2r);
            float zz = sigmoidf_((acc1[r] + bi2z) + bh2z);
            float nn = fast_tanh(fmaf(rr, bh2n, acc2[r] + bi2n));
            sh_h2[r*256 + tid] = (1.f - zz) * nn;
        }
        // -- phase 3: GEMM3 (q = h2 @ Wq) --
        float qacc[8];
#pragma unroll
        for (int r = 0; r < 8; r++) qacc[r] = 0.f;
#pragma unroll 1
        for (int tile = 0; tile < 16; tile++) {
            CP_WAIT0();
            __syncthreads();
            if (tile < 15) {
                const float* src = Wq + (tile+1)*4096;
                float* dst = shB + ((tile+1)&1)*12288;
#pragma unroll
                for (int p = 0; p < 4; p++) { int e = tid + p*256; cp16(dst + e*4, src + e*4); }
                CP_COMMIT();
            }
            const float* Bt = shB + (tile&1)*12288;
#pragma unroll
            for (int k4 = 0; k4 < 4; k4++) {
                float4 a[8];
#pragma unroll
                for (int r = 0; r < 8; r++)
                    a[r] = *(const float4*)(sh_h2 + r*256 + tile*16 + k4*4);
#pragma unroll
                for (int kk = 0; kk < 4; kk++) {
                    float bb = Bt[(k4*4 + kk)*256 + tid];
#pragma unroll
                    for (int r = 0; r < 8; r++) {
                        float av = (kk==0)?a[r].x:(kk==1)?a[r].y:(kk==2)?a[r].z:a[r].w;
                        qacc[r] = fmaf(av, bb, qacc[r]);
                    }
                }
            }
        }
#pragma unroll
        for (int r = 0; r < 8; r++) sh_q[r*256 + tid] = qacc[r];
        for (int i = tid; i < 800; i += 256) sh_su[i] = -1000000000.0f;
        // prefetch next step's W2T tile0 -> buf0
#pragma unroll
        for (int p = 0; p < 12; p++) { int e = tid + p*256; cp16(shB + e*4, W2T + e*4); }
        CP_COMMIT();
        __syncthreads();

        // -- phase 4: attention / argmax / log-softmax / state, warp w -> row w --
        {
            float4 q0 = *(const float4*)(sh_q + w*256 + lane*4);
            float4 q1 = *(const float4*)(sh_q + w*256 + 128 + lane*4);
            float4 v0 = *(const float4*)(sh_v + lane*4);
            float4 v1 = *(const float4*)(sh_v + 128 + lane*4);
            const float4* refrow = (const float4*)(REF + (size_t)(b0 + w)*Nn*Hh);
#pragma unroll 1
            for (int n = 0; n < Nn; n++) {
                if (sh_mask[w*100 + n]) continue;   // masked: exp->0, can't win argmax
                float4 r0 = __ldg(refrow + n*64 + lane);
                float4 r1 = __ldg(refrow + n*64 + 32 + lane);
                float s = tanh4dot(q0, r0, v0) + tanh4dot(q1, r1, v1);
#pragma unroll
                for (int o = 16; o; o >>= 1) s += __shfl_xor_sync(~0u, s, o);
                if (lane == 0) sh_su[w*100 + n] = 10.f * fast_tanh(s);
            }
            __syncwarp();
            float best = -INFINITY; int bi = 0x7fffffff;
            for (int n = lane; n < Nn; n += 32) {
                float u = sh_su[w*100 + n];
                if (u > best) { best = u; bi = n; }
            }
#pragma unroll
            for (int o = 16; o; o >>= 1) {
                float ov = __shfl_xor_sync(~0u, best, o);
                int   oi = __shfl_xor_sync(~0u, bi, o);
                if (ov > best || (ov == best && oi < bi)) { best = ov; bi = oi; }
            }
            float se = 0.f;
            for (int n = lane; n < Nn; n += 32) se += __expf(sh_su[w*100 + n] - best);
#pragma unroll
            for (int o = 16; o; o >>= 1) se += __shfl_xor_sync(~0u, se, o);
            ll += -__logf(se);
            if (lane == 0) {
                sh_nxt[w] = bi;
                sh_mask[w*100 + bi] = 1;
                sh_pi[w*100 + t] = (unsigned char)bi;
            }
            __syncwarp();
        }
        Dv -= 0.01f;
    }
    CP_WAIT0();
    __syncthreads();

    // -- tour cost + output, warp w -> row w --
    {
        float cs = 0.f;
        const float* xb = x + (size_t)(b0 + w)*Nn*2;
        for (int tt = lane; tt < Nn; tt += 32) {
            int a  = sh_pi[w*100 + tt];
            int cc = sh_pi[w*100 + ((tt == Nn-1) ? 0 : tt+1)];
            float dx = __ldg(xb + a*2)     - __ldg(xb + cc*2);
            float dy = __ldg(xb + a*2 + 1) - __ldg(xb + cc*2 + 1);
            cs += sqrtf(dx*dx + dy*dy);
        }
#pragma unroll
        for (int o = 16; o; o >>= 1) cs += __shfl_xor_sync(~0u, cs, o);
        if (lane == 0) { out[b0 + w] = cs; out[Bsz + b0 + w] = ll; }
    }
}

extern "C" void kernel_launch(void* const* d_in, const int* in_sizes, int n_in,
                              void* d_out, int out_size) {
    const float* x     = (const float*)d_in[0];
    const float* enc   = (const float*)d_in[1];
    const float* W_ih1 = (const float*)d_in[2];
    const float* b_ih1 = (const float*)d_in[4];
    const float* b_hh1 = (const float*)d_in[5];
    const float* W_ih2 = (const float*)d_in[6];
    const float* b_ih2 = (const float*)d_in[8];
    const float* b_hh2 = (const float*)d_in[9];
    const float* W_q   = (const float*)d_in[10];
    const float* W_ref = (const float*)d_in[11];
    const float* v     = (const float*)d_in[12];
    float* out = (float*)d_out;

    float *G, *REF, *G0, *MEAN, *W1T, *W2T, *BIAS0, *WD;
    cudaGetSymbolAddress((void**)&G,    g_G);
    cudaGetSymbolAddress((void**)&REF,  g_ref);
    cudaGetSymbolAddress((void**)&G0,   g_G0);
    cudaGetSymbolAddress((void**)&MEAN, g_mean);
    cudaGetSymbolAddress((void**)&W1T,  g_W1T);
    cudaGetSymbolAddress((void**)&W2T,  g_W2T);
    cudaGetSymbolAddress((void**)&BIAS0,g_bias0);
    cudaGetSymbolAddress((void**)&WD,   g_wD);

    cudaFuncSetAttribute(k_loop, cudaFuncAttributeMaxDynamicSharedMemorySize, SMEM_BYTES);

    k_prep<<<768, 256>>>(W_ih1, W_ih2, b_ih1);
    k_mean<<<Bsz, 256>>>(enc);
    k_sgemm<128,128,8,8><<<dim3(H3/128, (Bsz*Nn)/128), 256>>>(enc, W1T, b_ih1, G, Bsz*Nn, H3, Hh);
    k_sgemm<128,128,8,8><<<dim3(Hh/128, (Bsz*Nn)/128), 256>>>(enc, W_ref, nullptr, REF, Bsz*Nn, Hh, Hh);
    k_sgemm<64,64,4,4><<<dim3(H3/64, Bsz/64), 256>>>(MEAN, W1T, BIAS0, G0, Bsz, H3, Hh);
    k_loop<<<128, 256, SMEM_BYTES>>>(G, G0, REF, W2T, W_q, b_hh1, b_ih2, b_hh2, v, WD, x, out);
}